// round 2
// baseline (speedup 1.0000x reference)
#include <cuda_runtime.h>
#include <cstdint>

// Input:  x  (4, 64, 512, 512) fp32  -> flatten (BC=256, 512, 512)
// Output: [ll | lh | hl | hh], each (256, 256, 256) fp32, concatenated.
//
// Each thread handles a 2x8 input patch (2 rows x 2 float4 quads per row):
//   4 front-batched LDG.128 loads (MLP=4), then one float4 (STG.128) store
//   into each of the 4 output planes.

static constexpr int BC    = 256;          // 4 * 64
static constexpr int W_IN  = 512;
static constexpr int H_OUT = 256;
static constexpr int W_OUT = 256;
static constexpr int PLANE = BC * H_OUT * W_OUT;   // 16,777,216 elems per plane
static constexpr int QPR   = W_IN / 4;             // 128 float4 quads per input row
static constexpr int GPR   = QPR / 2;              // 64 groups (2 quads) per row
static constexpr long long TOTAL_GROUPS = (long long)BC * H_OUT * GPR; // 4,194,304

__global__ void __launch_bounds__(256) fast_dwt_kernel(
    const float4* __restrict__ x,
    float* __restrict__ out)
{
    long long idx = (long long)blockIdx.x * blockDim.x + threadIdx.x;
    if (idx >= TOTAL_GROUPS) return;

    int wg = (int)(idx % GPR);              // group within row (4 output cols)
    long long t = idx / GPR;
    int ho = (int)(t % H_OUT);
    int bc = (int)(t / H_OUT);

    // Input rows 2*ho and 2*ho+1, quad index base = 2*wg.
    long long q = ((long long)bc * 512 + 2 * ho) * QPR + 2 * wg;

    // Front-batched loads — 4 independent LDG.128 in flight.
    float4 r0a = x[q];
    float4 r0b = x[q + 1];
    float4 r1a = x[q + QPR];
    float4 r1b = x[q + QPR + 1];

    float4 ll, lh, hl, hh;

    // block 0: cols 0-1 of patch
    {
        float apb = r0a.x + r0a.y, amb = r0a.x - r0a.y;
        float cpd = r1a.x + r1a.y, cmd = r1a.x - r1a.y;
        ll.x = (apb + cpd) * 0.5f;  lh.x = (apb - cpd) * 0.5f;
        hl.x = (amb + cmd) * 0.5f;  hh.x = (amb - cmd) * 0.5f;
    }
    // block 1: cols 2-3
    {
        float apb = r0a.z + r0a.w, amb = r0a.z - r0a.w;
        float cpd = r1a.z + r1a.w, cmd = r1a.z - r1a.w;
        ll.y = (apb + cpd) * 0.5f;  lh.y = (apb - cpd) * 0.5f;
        hl.y = (amb + cmd) * 0.5f;  hh.y = (amb - cmd) * 0.5f;
    }
    // block 2: cols 4-5
    {
        float apb = r0b.x + r0b.y, amb = r0b.x - r0b.y;
        float cpd = r1b.x + r1b.y, cmd = r1b.x - r1b.y;
        ll.z = (apb + cpd) * 0.5f;  lh.z = (apb - cpd) * 0.5f;
        hl.z = (amb + cmd) * 0.5f;  hh.z = (amb - cmd) * 0.5f;
    }
    // block 3: cols 6-7
    {
        float apb = r0b.z + r0b.w, amb = r0b.z - r0b.w;
        float cpd = r1b.z + r1b.w, cmd = r1b.z - r1b.w;
        ll.w = (apb + cpd) * 0.5f;  lh.w = (apb - cpd) * 0.5f;
        hl.w = (amb + cmd) * 0.5f;  hh.w = (amb - cmd) * 0.5f;
    }

    // Output offset (floats): plane-local (bc, ho, 4*wg)
    long long o = ((long long)bc * H_OUT + ho) * W_OUT + 4 * wg;
    *(float4*)(out + 0LL * PLANE + o) = ll;
    *(float4*)(out + 1LL * PLANE + o) = lh;
    *(float4*)(out + 2LL * PLANE + o) = hl;
    *(float4*)(out + 3LL * PLANE + o) = hh;
}

extern "C" void kernel_launch(void* const* d_in, const int* in_sizes, int n_in,
                              void* d_out, int out_size)
{
    const float4* x = (const float4*)d_in[0];
    float* out = (float*)d_out;

    const int threads = 256;
    const int blocks = (int)((TOTAL_GROUPS + threads - 1) / threads);
    fast_dwt_kernel<<<blocks, threads>>>(x, out);
}

// round 3
// speedup vs baseline: 1.0205x; 1.0205x over previous
#include <cuda_runtime.h>
#include <cstdint>

// Input:  x  (4, 64, 512, 512) fp32  -> flatten (BC=256, 512, 512)
// Output: [ll | lh | hl | hh], each (256, 256, 256) fp32, concatenated.
//
// R1 structure (best so far): each thread reads one float4 from rows 2h and
// 2h+1 (two 2x2 Haar blocks), writes a float2 to each of the 4 output planes.
// R3 adds streaming cache hints (no reuse anywhere) and an exact grid (no
// tail branch).

static constexpr int BC    = 256;          // 4 * 64
static constexpr int W_IN  = 512;
static constexpr int H_OUT = 256;
static constexpr int W_OUT = 256;
static constexpr int PLANE = BC * H_OUT * W_OUT;        // 16,777,216 elems/plane
static constexpr int W4    = W_IN / 4;                  // 128 float4 per input row
static constexpr long long TOTAL_PAIRS = (long long)BC * H_OUT * (W_OUT / 2); // 8,388,608 (multiple of 256)

__device__ __forceinline__ float4 ldcs4(const float4* p) {
    float4 v;
    asm volatile("ld.global.cs.v4.f32 {%0,%1,%2,%3}, [%4];"
                 : "=f"(v.x), "=f"(v.y), "=f"(v.z), "=f"(v.w) : "l"(p));
    return v;
}

__device__ __forceinline__ void stcs2(float* p, float2 v) {
    asm volatile("st.global.cs.v2.f32 [%0], {%1,%2};"
                 :: "l"(p), "f"(v.x), "f"(v.y) : "memory");
}

__global__ void __launch_bounds__(256) fast_dwt_kernel(
    const float4* __restrict__ x,
    float* __restrict__ out)
{
    // Exact grid: no bounds check needed.
    unsigned idx = blockIdx.x * blockDim.x + threadIdx.x;   // < 8,388,608

    unsigned wq = idx & (W4 - 1);          // quad within row (W4=128, pow2)
    unsigned t  = idx >> 7;
    unsigned ho = t & (H_OUT - 1);         // 256, pow2
    unsigned bc = t >> 8;

    // Input rows 2*ho and 2*ho+1, as float4 indices.
    unsigned row0 = (bc * 512u + 2u * ho) * W4;
    float4 r0 = ldcs4(x + row0 + wq);
    float4 r1 = ldcs4(x + row0 + W4 + wq);

    float2 ll, lh, hl, hh;
    {
        float apb = r0.x + r0.y, amb = r0.x - r0.y;
        float cpd = r1.x + r1.y, cmd = r1.x - r1.y;
        ll.x = (apb + cpd) * 0.5f;  lh.x = (apb - cpd) * 0.5f;
        hl.x = (amb + cmd) * 0.5f;  hh.x = (amb - cmd) * 0.5f;
    }
    {
        float apb = r0.z + r0.w, amb = r0.z - r0.w;
        float cpd = r1.z + r1.w, cmd = r1.z - r1.w;
        ll.y = (apb + cpd) * 0.5f;  lh.y = (apb - cpd) * 0.5f;
        hl.y = (amb + cmd) * 0.5f;  hh.y = (amb - cmd) * 0.5f;
    }

    // Output offset within a plane (floats): (bc, ho, 2*wq)
    unsigned o = (bc * H_OUT + ho) * W_OUT + 2u * wq;
    stcs2(out + 0u * PLANE + o, ll);
    stcs2(out + 1u * PLANE + o, lh);
    stcs2(out + 2u * PLANE + o, hl);
    stcs2(out + 3u * PLANE + o, hh);
}

extern "C" void kernel_launch(void* const* d_in, const int* in_sizes, int n_in,
                              void* d_out, int out_size)
{
    const float4* x = (const float4*)d_in[0];
    float* out = (float*)d_out;

    const int threads = 256;
    const int blocks = (int)(TOTAL_PAIRS / threads);   // exact
    fast_dwt_kernel<<<blocks, threads>>>(x, out);
}